// round 16
// baseline (speedup 1.0000x reference)
#include <cuda_runtime.h>
#include <cuda_fp16.h>

typedef unsigned int u32;

#define TT 1024
#define BB 512
#define FI 128
#define UU 256
#define PP 1024        // 4*U permuted: 16-block b16=P>>4; c<8 -> i,f ; c>=8 -> o,g
#define RC_CTAS 256    // 16 batch groups x 16 n-tiles; M=32, N=64, K=256(h)+128(x)

// ---------------- device scratch ----------------
__device__ __half g_WT[PP * FI];          // W^T permuted [P][f]
__device__ __half g_RT[PP * UU];          // R^T permuted [P][k]
__device__ __half g_h[2][BB * UU];        // h state, double buffered
__device__ float g_bp[PP];
__device__ __half g_x16[(size_t)TT * BB * FI];  // x transposed+fp16: [t][b][f]
__device__ unsigned g_slot[16][16];       // per-group, per-CTA step counters

// ---------------- helpers ----------------
__device__ __forceinline__ u32 s2u(const void* p) {
    u32 a;
    asm("{ .reg .u64 t; cvta.to.shared.u64 t, %1; cvt.u32.u64 %0, t; }" : "=r"(a) : "l"(p));
    return a;
}
__device__ __forceinline__ void ldsm4(u32 addr, u32* r) {
    asm volatile("ldmatrix.sync.aligned.m8n8.x4.shared.b16 {%0,%1,%2,%3}, [%4];"
                 : "=r"(r[0]), "=r"(r[1]), "=r"(r[2]), "=r"(r[3]) : "r"(addr));
}
__device__ __forceinline__ void mma16816(float* c, const u32* a, u32 b0, u32 b1) {
    asm volatile(
        "mma.sync.aligned.m16n8k16.row.col.f32.f16.f16.f32 "
        "{%0,%1,%2,%3},{%4,%5,%6,%7},{%8,%9},{%0,%1,%2,%3};"
        : "+f"(c[0]), "+f"(c[1]), "+f"(c[2]), "+f"(c[3])
        : "r"(a[0]), "r"(a[1]), "r"(a[2]), "r"(a[3]), "r"(b0), "r"(b1));
}
__device__ __forceinline__ void cpasync16(u32 smem_dst, const void* gsrc) {
    asm volatile("cp.async.cg.shared.global [%0], [%1], 16;"
                 :: "r"(smem_dst), "l"(gsrc) : "memory");
}
#define CP_COMMIT() asm volatile("cp.async.commit_group;" ::: "memory")
#define CP_WAIT_ALL() asm volatile("cp.async.wait_group 0;" ::: "memory")

__device__ __forceinline__ float sig_fast(float x) {
    return __fdividef(1.0f, 1.0f + __expf(-x));
}
__device__ __forceinline__ float tanh_acc(float x) {
    return __fdividef(2.0f, 1.0f + __expf(-2.0f * x)) - 1.0f;
}
__device__ __forceinline__ int origcol(int P) {   // permuted col -> keras col
    int blk = P >> 4, c = P & 15;
    int u = 4 * blk + ((c >> 1) & 3);
    int g = ((c >> 3) << 1) | (c & 1);            // 0:i 1:f 2:o 3:g
    return g * UU + u;
}

// ================= prep: weights / bias / h0 =================
__global__ void lstm_prep(const float* __restrict__ W, const float* __restrict__ R,
                          const float* __restrict__ bias, const float* __restrict__ h0) {
    int i = blockIdx.x * blockDim.x + threadIdx.x;
    if (i < PP * FI) {
        int P = i >> 7, f = i & 127;
        g_WT[i] = __float2half_rn(W[f * PP + origcol(P)]);
    } else if (i < PP * FI + PP * UU) {
        int j = i - PP * FI;
        int P = j >> 8, k = j & 255;
        g_RT[j] = __float2half_rn(R[k * PP + origcol(P)]);
    } else if (i < PP * FI + PP * UU + PP) {
        int P = i - PP * FI - PP * UU;
        g_bp[P] = bias[origcol(P)];
    } else if (i < PP * FI + PP * UU + PP + BB * UU) {
        int j = i - PP * FI - PP * UU - PP;
        g_h[0][j] = __float2half_rn(h0[j]);
    }
}

// ================= prep: x -> fp16 [t][b][f] =================
__global__ void lstm_prep_x(const float* __restrict__ x) {
    const int bx = blockIdx.x;           // t*BB + b
    const int t = bx >> 9;
    const int b = bx & (BB - 1);
    const int f = threadIdx.x;           // 128 threads
    g_x16[(size_t)bx * FI + f] = __float2half_rn(x[((size_t)b * TT + t) * FI + f]);
}

// ================= cleanup: reset barrier slots (graph-replay safety) =================
__global__ void lstm_cleanup() {
    ((unsigned*)g_slot)[threadIdx.x] = 0;     // 256 threads = 16*16 slots
}

// ================= persistent recurrence (fused x@W + h@R) =================
#define S_H0 0                 // h buffer 0: 32 rows * 528B = 16896
#define S_H1 16896             // h buffer 1
#define S_W  33792             // W^T slice: 64 n * 272B = 17408
#define S_X0 51200             // x buffer 0: 32 rows * 272B = 8704
#define S_X1 59904             // x buffer 1
#define R_SMEM (68608 + 32)

__global__ __launch_bounds__(256, 2) void lstm_recur(const float* __restrict__ c0,
                                                     float* __restrict__ out) {
    extern __shared__ char sb[];
    const u32 sbase = s2u(sb);
    const int tid = threadIdx.x;
    const int w = tid >> 5, lane = tid & 31;
    const int mt = blockIdx.x & 15;
    const int nt = blockIdx.x >> 4;
    const int b_base = mt * 32;
    const int n0 = nt * 64;
    const int mchunk = w & 1;          // 2 x 16 rows
    const int nchunk = w >> 1;         // 4 x 16 cols
    const int q = lane & 3;
    const int row_l = lane >> 2;

    // --- init: stage R^T [64 n][256 k] across h-buffers, frags -> regs
    for (int it = 0; it < 8; it++) {
        int idx = tid + it * 256;
        int n = idx >> 5, ku = idx & 31;
        *(uint4*)(sb + n * 528 + ku * 16) = *(const uint4*)&g_RT[(n0 + n) * UU + ku * 8];
    }
    __syncthreads();
    const int rB = nchunk * 16 + (lane & 7) + 8 * ((lane >> 4) & 1);
    const int cB = 8 * ((lane >> 3) & 1);
    u32 bh[16][4];
    {
        const u32 bAddr = sbase + rB * 528 + cB * 2;
#pragma unroll
        for (int k = 0; k < 16; k++) ldsm4(bAddr + k * 32, bh[k]);
    }
    __syncthreads();

    // --- init: stage W^T slice [64 n][128 k] (persistent) + x(0)
    for (int it = 0; it < 4; it++) {
        int idx = tid + it * 256;
        int n = idx >> 4, ku = idx & 15;
        *(uint4*)(sb + S_W + n * 272 + ku * 16) = *(const uint4*)&g_WT[(n0 + n) * FI + ku * 8];
    }
    for (int it = 0; it < 2; it++) {
        int idx = tid + it * 256;
        int r = idx >> 4, ku = idx & 15;
        *(uint4*)(sb + S_X0 + r * 272 + ku * 16) =
            *(const uint4*)&g_x16[((size_t)b_base + r) * FI + ku * 8];
    }
    const u32 bAddrW = sbase + S_W + rB * 272 + cB * 2;

    // A lane offsets
    const int rA = mchunk * 16 + (lane & 7) + 8 * ((lane >> 3) & 1);
    const int cA = 8 * ((lane >> 4) & 1);
    const u32 aOffH = rA * 528 + cA * 2;
    const u32 aOffX = rA * 272 + cA * 2;

    // thread owns all 4 gates of unit u for rows br0, br0+8
    const int B16 = nt * 4 + nchunk;
    const int u = 4 * B16 + q;
    const int br0 = b_base + mchunk * 16 + row_l;
    float c_reg[2] = { c0[br0 * UU + u], c0[(br0 + 8) * UU + u] };
    const float2 b_if = *(const float2*)&g_bp[16 * B16 + 2 * q];
    const float2 b_og = *(const float2*)&g_bp[16 * B16 + 8 + 2 * q];

    unsigned* const myslot = &g_slot[mt][nt];
    unsigned* const slots = &g_slot[mt][0];

    for (int t = 0; t < TT; t++) {
        // stage h(t) via cp.async into h buffer t&1
        const __half* hsrc = g_h[t & 1];
        const u32 hbuf = (u32)(t & 1) * 16896u;
        for (int it = 0; it < 4; it++) {
            int idx = tid + it * 256;
            int r = idx >> 5, ku = idx & 31;
            cpasync16(sbase + hbuf + r * 528 + ku * 16, &hsrc[(b_base + r) * UU + ku * 8]);
        }
        CP_COMMIT();
        CP_WAIT_ALL();        // also drains the x(t) copies from last iteration
        __syncthreads();

        float C[2][4];
#pragma unroll
        for (int n = 0; n < 2; n++)
#pragma unroll
            for (int r = 0; r < 4; r++) C[n][r] = 0.0f;

        // h @ R : 16 k-steps, B in regs
        const u32 aAddrH = sbase + hbuf + aOffH;
#pragma unroll
        for (int k = 0; k < 16; k++) {
            u32 a0[4];
            ldsm4(aAddrH + k * 32, a0);
            mma16816(C[0], a0, bh[k][0], bh[k][1]);
            mma16816(C[1], a0, bh[k][2], bh[k][3]);
        }
        // x_t @ W : 8 k-steps
        const u32 aAddrX = sbase + ((t & 1) ? S_X1 : S_X0) + aOffX;
#pragma unroll
        for (int k = 0; k < 8; k++) {
            u32 a0[4], bw[4];
            ldsm4(aAddrX + k * 32, a0);
            ldsm4(bAddrW + k * 32, bw);
            mma16816(C[0], a0, bw[0], bw[1]);
            mma16816(C[1], a0, bw[2], bw[3]);
        }

        // gates
        __half* hdst = g_h[(t + 1) & 1];
#pragma unroll
        for (int j = 0; j < 2; j++) {
            const int rr = 2 * j;
            const float zi = C[0][rr]     + b_if.x;
            const float zf = C[0][rr + 1] + b_if.y;
            const float zo = C[1][rr]     + b_og.x;
            const float zg = C[1][rr + 1] + b_og.y;
            const float ig = sig_fast(zi);
            const float fg = sig_fast(zf);
            const float og = sig_fast(zo);
            const float gg = tanh_acc(zg);
            const float c = fmaf(fg, c_reg[j], ig * gg);
            c_reg[j] = c;
            const float h = og * tanh_acc(c);
            const int br = br0 + 8 * j;
            hdst[br * UU + u] = __float2half_rn(h);
            if (t == TT - 1) out[br * UU + u] = h;
        }
        if (t == TT - 1) break;          // nobody consumes h(TT): skip last barrier
        __syncthreads();                 // all h writes issued before publishing

        // flat barrier: publish own counter, prefetch x(t+1), poll peers lane-parallel
        const unsigned need = (unsigned)(t + 1);
        if (tid == 0)
            asm volatile("st.release.gpu.global.u32 [%0], %1;"
                         :: "l"(myslot), "r"(need) : "memory");
        {   // x staging is barrier-independent
            const u32 xbuf = ((t + 1) & 1) ? S_X1 : S_X0;
            for (int it = 0; it < 2; it++) {
                int idx = tid + it * 256;
                int r = idx >> 4, ku = idx & 15;
                cpasync16(sbase + xbuf + r * 272 + ku * 16,
                          &g_x16[((size_t)(t + 1) * BB + b_base + r) * FI + ku * 8]);
            }
            CP_COMMIT();
        }
        if (w == 0) {
            bool ok;
            do {
                unsigned v = need;
                if (lane < 16)
                    asm volatile("ld.acquire.gpu.global.u32 %0, [%1];"
                                 : "=r"(v) : "l"(&slots[lane]) : "memory");
                ok = __all_sync(0xFFFFFFFFu, v >= need);
            } while (!ok);
        }
        __syncthreads();
    }
}

extern "C" void kernel_launch(void* const* d_in, const int* in_sizes, int n_in,
                              void* d_out, int out_size) {
    const float* x    = (const float*)d_in[0];
    const float* W    = (const float*)d_in[1];
    const float* R    = (const float*)d_in[2];
    const float* bias = (const float*)d_in[3];
    const float* h0   = (const float*)d_in[4];
    const float* c0   = (const float*)d_in[5];
    float* out = (float*)d_out;

    cudaFuncSetAttribute(lstm_recur, cudaFuncAttributeMaxDynamicSharedMemorySize, R_SMEM);

    const int prep_total = PP * FI + PP * UU + PP + BB * UU;
    lstm_prep<<<(prep_total + 255) / 256, 256>>>(W, R, bias, h0);
    lstm_prep_x<<<TT * BB, FI>>>(x);
    lstm_recur<<<RC_CTAS, 256, R_SMEM>>>(c0, out);
    lstm_cleanup<<<1, 256>>>();          // reset barrier slots for graph replay
}

// round 17
// speedup vs baseline: 1.5063x; 1.5063x over previous
#include <cuda_runtime.h>
#include <cuda_fp16.h>

typedef unsigned int u32;

#define TT 1024
#define BB 512
#define FI 128
#define UU 256
#define PP 1024        // 4*U permuted: 16-block b16=P>>4; c<8 -> i,f ; c>=8 -> o,g
#define RC_CTAS 256    // 16 batch groups x 16 n-tiles; M=32, N=64, K=256(h)+128(x)

// ---------------- device scratch ----------------
__device__ __half g_WT[PP * FI];          // W^T permuted [P][f]
__device__ __half g_RT[PP * UU];          // R^T permuted [P][k]
__device__ __half g_h[2][BB * UU];        // h state, double buffered
__device__ float g_bp[PP];
__device__ __half g_x16[(size_t)TT * BB * FI];  // x transposed+fp16: [t][b][f]
__device__ unsigned g_cnt[16 * 32];       // per-group barrier (128B padded)
__device__ unsigned g_flag[16 * 32];

// ---------------- helpers ----------------
__device__ __forceinline__ u32 s2u(const void* p) {
    u32 a;
    asm("{ .reg .u64 t; cvta.to.shared.u64 t, %1; cvt.u32.u64 %0, t; }" : "=r"(a) : "l"(p));
    return a;
}
__device__ __forceinline__ void ldsm4(u32 addr, u32* r) {
    asm volatile("ldmatrix.sync.aligned.m8n8.x4.shared.b16 {%0,%1,%2,%3}, [%4];"
                 : "=r"(r[0]), "=r"(r[1]), "=r"(r[2]), "=r"(r[3]) : "r"(addr));
}
__device__ __forceinline__ void mma16816(float* c, const u32* a, u32 b0, u32 b1) {
    asm volatile(
        "mma.sync.aligned.m16n8k16.row.col.f32.f16.f16.f32 "
        "{%0,%1,%2,%3},{%4,%5,%6,%7},{%8,%9},{%0,%1,%2,%3};"
        : "+f"(c[0]), "+f"(c[1]), "+f"(c[2]), "+f"(c[3])
        : "r"(a[0]), "r"(a[1]), "r"(a[2]), "r"(a[3]), "r"(b0), "r"(b1));
}
__device__ __forceinline__ float tanh_hw(float x) {
    float y;
    asm("tanh.approx.f32 %0, %1;" : "=f"(y) : "f"(x));
    return y;
}
__device__ __forceinline__ float sig_hw(float x) {        // 0.5*tanh(x/2)+0.5
    return fmaf(0.5f, tanh_hw(0.5f * x), 0.5f);
}
__device__ __forceinline__ int origcol(int P) {   // permuted col -> keras col
    int blk = P >> 4, c = P & 15;
    int u = 4 * blk + ((c >> 1) & 3);
    int g = ((c >> 3) << 1) | (c & 1);            // 0:i 1:f 2:o 3:g
    return g * UU + u;
}

// ================= prep: weights / bias / h0 =================
__global__ void lstm_prep(const float* __restrict__ W, const float* __restrict__ R,
                          const float* __restrict__ bias, const float* __restrict__ h0) {
    int i = blockIdx.x * blockDim.x + threadIdx.x;
    if (i < PP * FI) {
        int P = i >> 7, f = i & 127;
        g_WT[i] = __float2half_rn(W[f * PP + origcol(P)]);
    } else if (i < PP * FI + PP * UU) {
        int j = i - PP * FI;
        int P = j >> 8, k = j & 255;
        g_RT[j] = __float2half_rn(R[k * PP + origcol(P)]);
    } else if (i < PP * FI + PP * UU + PP) {
        int P = i - PP * FI - PP * UU;
        g_bp[P] = bias[origcol(P)];
    } else if (i < PP * FI + PP * UU + PP + BB * UU) {
        int j = i - PP * FI - PP * UU - PP;
        g_h[0][j] = __float2half_rn(h0[j]);
    }
}

// ================= prep: x -> fp16 [t][b][f] =================
__global__ void lstm_prep_x(const float* __restrict__ x) {
    const int bx = blockIdx.x;           // t*BB + b
    const int t = bx >> 9;
    const int b = bx & (BB - 1);
    const int f = threadIdx.x;           // 128 threads
    g_x16[(size_t)bx * FI + f] = __float2half_rn(x[((size_t)b * TT + t) * FI + f]);
}

// ================= persistent recurrence (fused x@W + h@R) =================
#define S_H0 0                 // h buffer 0: 32 rows * 528B = 16896
#define S_H1 16896             // h buffer 1
#define S_W  33792             // W^T slice: 64 n * 272B = 17408
#define S_X0 51200             // x buffer 0: 32 rows * 272B = 8704
#define S_X1 59904             // x buffer 1
#define R_SMEM (68608 + 32)

__global__ __launch_bounds__(256, 2) void lstm_recur(const float* __restrict__ c0,
                                                     float* __restrict__ out) {
    extern __shared__ char sb[];
    const u32 sbase = s2u(sb);
    const int tid = threadIdx.x;
    const int w = tid >> 5, lane = tid & 31;
    const int mt = blockIdx.x & 15;
    const int nt = blockIdx.x >> 4;
    const int b_base = mt * 32;
    const int n0 = nt * 64;
    const int mchunk = w & 1;          // 2 x 16 rows
    const int nchunk = w >> 1;         // 4 x 16 cols
    const int q = lane & 3;
    const int row_l = lane >> 2;

    // --- init: stage R^T [64 n][256 k] across h-buffers, frags -> regs
    for (int it = 0; it < 8; it++) {
        int idx = tid + it * 256;
        int n = idx >> 5, ku = idx & 31;
        *(uint4*)(sb + n * 528 + ku * 16) = *(const uint4*)&g_RT[(n0 + n) * UU + ku * 8];
    }
    __syncthreads();
    const int rB = nchunk * 16 + (lane & 7) + 8 * ((lane >> 4) & 1);
    const int cB = 8 * ((lane >> 3) & 1);
    u32 bh[16][4];
    {
        const u32 bAddr = sbase + rB * 528 + cB * 2;
#pragma unroll
        for (int k = 0; k < 16; k++) ldsm4(bAddr + k * 32, bh[k]);
    }
    __syncthreads();

    // --- init: stage W^T slice [64 n][128 k] (persistent) + x(0)
    for (int it = 0; it < 4; it++) {
        int idx = tid + it * 256;
        int n = idx >> 4, ku = idx & 15;
        *(uint4*)(sb + S_W + n * 272 + ku * 16) = *(const uint4*)&g_WT[(n0 + n) * FI + ku * 8];
    }
    for (int it = 0; it < 2; it++) {
        int idx = tid + it * 256;
        int r = idx >> 4, ku = idx & 15;
        *(uint4*)(sb + S_X0 + r * 272 + ku * 16) =
            *(const uint4*)&g_x16[((size_t)b_base + r) * FI + ku * 8];
    }
    const u32 bAddrW = sbase + S_W + rB * 272 + cB * 2;

    // A lane offsets
    const int rA = mchunk * 16 + (lane & 7) + 8 * ((lane >> 3) & 1);
    const int cA = 8 * ((lane >> 4) & 1);
    const u32 aOffH = rA * 528 + cA * 2;
    const u32 aOffX = rA * 272 + cA * 2;

    // thread owns all 4 gates of unit u for rows br0, br0+8
    const int B16 = nt * 4 + nchunk;
    const int u = 4 * B16 + q;
    const int br0 = b_base + mchunk * 16 + row_l;
    float c_reg[2] = { c0[br0 * UU + u], c0[(br0 + 8) * UU + u] };
    const float2 b_if = *(const float2*)&g_bp[16 * B16 + 2 * q];
    const float2 b_og = *(const float2*)&g_bp[16 * B16 + 8 + 2 * q];

    unsigned* const cnt = &g_cnt[mt * 32];
    unsigned* const flag = &g_flag[mt * 32];
    unsigned sense = 0;

    // --- prologue: C = x(0) @ W (x0 + W staged above)
    __syncthreads();
    float C[2][4];
#pragma unroll
    for (int n = 0; n < 2; n++)
#pragma unroll
        for (int r = 0; r < 4; r++) C[n][r] = 0.0f;
    {
        const u32 aAddrX = sbase + S_X0 + aOffX;
#pragma unroll
        for (int k = 0; k < 8; k++) {
            u32 a0[4], bw[4];
            ldsm4(aAddrX + k * 32, a0);
            ldsm4(bAddrW + k * 32, bw);
            mma16816(C[0], a0, bw[0], bw[1]);
            mma16816(C[1], a0, bw[2], bw[3]);
        }
    }

    for (int t = 0; t < TT; t++) {
        // stage h(t): 1024 uint4 into h buffer t&1
        const __half* hsrc = g_h[t & 1];
        const u32 hbuf = (u32)(t & 1) * 16896u;
        for (int it = 0; it < 4; it++) {
            int idx = tid + it * 256;
            int r = idx >> 5, ku = idx & 31;
            *(uint4*)(sb + hbuf + r * 528 + ku * 16) =
                *(const uint4*)&hsrc[(b_base + r) * UU + ku * 8];
        }
        __syncthreads();

        // h @ R : 16 k-steps, accumulate into C (which holds x_t @ W)
        const u32 aAddrH = sbase + hbuf + aOffH;
#pragma unroll
        for (int k = 0; k < 16; k++) {
            u32 a0[4];
            ldsm4(aAddrH + k * 32, a0);
            mma16816(C[0], a0, bh[k][0], bh[k][1]);
            mma16816(C[1], a0, bh[k][2], bh[k][3]);
        }

        // gates (HW tanh path)
        __half* hdst = g_h[(t + 1) & 1];
#pragma unroll
        for (int j = 0; j < 2; j++) {
            const int rr = 2 * j;
            const float zi = C[0][rr]     + b_if.x;
            const float zf = C[0][rr + 1] + b_if.y;
            const float zo = C[1][rr]     + b_og.x;
            const float zg = C[1][rr + 1] + b_og.y;
            const float ig = sig_hw(zi);
            const float fg = sig_hw(zf);
            const float og = sig_hw(zo);
            const float gg = tanh_hw(zg);
            const float c = fmaf(fg, c_reg[j], ig * gg);
            c_reg[j] = c;
            const float h = og * tanh_hw(c);
            const int br = br0 + 8 * j;
            hdst[br * UU + u] = __float2half_rn(h);
            if (t == TT - 1) out[br * UU + u] = h;
        }
        __syncthreads();   // h global writes done; h smem reads done

        // publish (always — 1024 flips restore flag for graph replay)
        sense ^= 1;
        if (tid == 0) {
            unsigned old;
            asm volatile("atom.add.acq_rel.gpu.global.u32 %0, [%1], 1;"
                         : "=r"(old) : "l"(cnt) : "memory");
            if (old == 15) {
                asm volatile("st.relaxed.gpu.global.u32 [%0], 0;" :: "l"(cnt) : "memory");
                unsigned tmp;
                asm volatile("atom.exch.release.gpu.global.b32 %0, [%1], %2;"
                             : "=r"(tmp) : "l"(flag), "r"(sense) : "memory");
                (void)tmp;
            }
        }
        if (t == TT - 1) break;   // nobody consumes h(TT): skip x-stage/Cx/poll

        // stage x(t+1) (barrier-independent), then compute next C = x(t+1)@W
        const u32 xbuf = ((t + 1) & 1) ? S_X1 : S_X0;
        for (int it = 0; it < 2; it++) {
            int idx = tid + it * 256;
            int r = idx >> 4, ku = idx & 15;
            *(uint4*)(sb + xbuf + r * 272 + ku * 16) =
                *(const uint4*)&g_x16[((size_t)(t + 1) * BB + b_base + r) * FI + ku * 8];
        }
        __syncthreads();   // x staged for all warps

#pragma unroll
        for (int n = 0; n < 2; n++)
#pragma unroll
            for (int r = 0; r < 4; r++) C[n][r] = 0.0f;
        {
            const u32 aAddrX = sbase + xbuf + aOffX;
#pragma unroll
            for (int k = 0; k < 8; k++) {
                u32 a0[4], bw[4];
                ldsm4(aAddrX + k * 32, a0);
                ldsm4(bAddrW + k * 32, bw);
                mma16816(C[0], a0, bw[0], bw[1]);
                mma16816(C[1], a0, bw[2], bw[3]);
            }
        }

        // poll peers' flag
        if (tid == 0) {
            unsigned f;
            do {
                asm volatile("ld.acquire.gpu.global.u32 %0, [%1];"
                             : "=r"(f) : "l"(flag) : "memory");
            } while (f != sense);
        }
        __syncthreads();
    }
}

extern "C" void kernel_launch(void* const* d_in, const int* in_sizes, int n_in,
                              void* d_out, int out_size) {
    const float* x    = (const float*)d_in[0];
    const float* W    = (const float*)d_in[1];
    const float* R    = (const float*)d_in[2];
    const float* bias = (const float*)d_in[3];
    const float* h0   = (const float*)d_in[4];
    const float* c0   = (const float*)d_in[5];
    float* out = (float*)d_out;

    cudaFuncSetAttribute(lstm_recur, cudaFuncAttributeMaxDynamicSharedMemorySize, R_SMEM);

    const int prep_total = PP * FI + PP * UU + PP + BB * UU;
    lstm_prep<<<(prep_total + 255) / 256, 256>>>(W, R, bias, h0);
    lstm_prep_x<<<TT * BB, FI>>>(x);
    lstm_recur<<<RC_CTAS, 256, R_SMEM>>>(c0, out);
}